// round 6
// baseline (speedup 1.0000x reference)
#include <cuda_runtime.h>
#include <cuda_bf16.h>
#include <cstdint>

// CIN (xDeepFM) fused 3-layer kernel via mma.sync (HMMA) bf16 3-term split.
// Round 5: MMA RAW-distance reordering + batched ldsm + phase-structured chunk.
// GEMM view per layer: C[(b,d), h] = sum_k Z[(b,d),k] * W[k,h],
//   Z[(b,d), f*fk+g] = x0[b,f,d] * state[b,g,d].
// CTA = 4 batches -> M=128 rows (b_local*32 + d), N=128 (h), K = 32*fk.

#define NT 256
#define KCH 576            // total 16-wide k chunks: 64 + 256 + 256
#define CHUNK_GBYTES 8192  // compact gmem chunk: 2 terms * 128n * 16k * 2B
#define WROW 48            // padded smem bytes per n-row (16k bf16 = 32B -> 48B)
#define WTERM (128 * WROW) // 6144
#define WSTAGE (2 * WTERM) // 12288

// smem byte offsets
#define SM_X0T   0                  // 128 rows * 36 f32 = 18432
#define SM_ST    18432              // 128 rows * 132 f32 = 67584
#define SM_W     86016              // 2 stages * 12288 = 24576
#define SM_BIAS  110592             // 384 f32 = 1536
#define SMEM_TOTAL 112128

__device__ __align__(16) unsigned char WT_buf[KCH * CHUNK_GBYTES]; // 4.5 MB

// ------------- helpers -------------
__device__ __forceinline__ uint32_t smem_u32(const void* p) {
    uint32_t a;
    asm("{ .reg .u64 t; cvta.to.shared.u64 t, %1; cvt.u32.u64 %0, t; }" : "=r"(a) : "l"(p));
    return a;
}
__device__ __forceinline__ uint32_t pkbf(float lo, float hi) {
    uint32_t r;  // first asm operand -> high half
    asm("cvt.rn.bf16x2.f32 %0, %1, %2;" : "=r"(r) : "f"(hi), "f"(lo));
    return r;
}
__device__ __forceinline__ float bflo(uint32_t p) { return __uint_as_float(p << 16); }
__device__ __forceinline__ float bfhi(uint32_t p) { return __uint_as_float(p & 0xffff0000u); }

__device__ __forceinline__ void ldsm4(uint32_t a, uint32_t& r0, uint32_t& r1,
                                      uint32_t& r2, uint32_t& r3) {
    asm volatile("ldmatrix.sync.aligned.m8n8.x4.shared.b16 {%0,%1,%2,%3}, [%4];"
                 : "=r"(r0), "=r"(r1), "=r"(r2), "=r"(r3) : "r"(a));
}
__device__ __forceinline__ void mma16816(float* c, const uint32_t* a, uint32_t b0, uint32_t b1) {
    asm volatile("mma.sync.aligned.m16n8k16.row.col.f32.bf16.bf16.f32 "
                 "{%0,%1,%2,%3}, {%4,%5,%6,%7}, {%8,%9}, {%0,%1,%2,%3};"
                 : "+f"(c[0]), "+f"(c[1]), "+f"(c[2]), "+f"(c[3])
                 : "r"(a[0]), "r"(a[1]), "r"(a[2]), "r"(a[3]), "r"(b0), "r"(b1));
}

// ------------- prep: split W -> bf16 hi/lo, chunked [chunk][term][n][k] -------------
__global__ void prep_w(const float* __restrict__ W0, const float* __restrict__ W1,
                       const float* __restrict__ W2) {
    int i = blockIdx.x * blockDim.x + threadIdx.x;   // over 9216*128
    if (i >= 9216 * 128) return;
    int k = i >> 7, n = i & 127;
    float w;
    if (k < 1024)      w = W0[k * 128 + n];
    else if (k < 5120) w = W1[(k - 1024) * 128 + n];
    else               w = W2[(k - 5120) * 128 + n];
    __nv_bfloat16 hb = __float2bfloat16(w);
    __nv_bfloat16 lb = __float2bfloat16(w - __bfloat162float(hb));
    int c = k >> 4, kk = k & 15;
    unsigned char* base = WT_buf + (size_t)c * CHUNK_GBYTES + n * 32 + kk * 2;
    *(__nv_bfloat16*)(base)        = hb;   // term 0
    *(__nv_bfloat16*)(base + 4096) = lb;   // term 1
}

// ------------- main kernel -------------
__global__ void __launch_bounds__(NT, 2)
cin_hmma_kernel(const float* __restrict__ X,
                const float* __restrict__ B0, const float* __restrict__ B1,
                const float* __restrict__ B2, float* __restrict__ out)
{
    extern __shared__ __align__(16) char smem[];
    float* x0t  = (float*)(smem + SM_X0T);   // [row][36] (f stride)
    float* st   = (float*)(smem + SM_ST);    // [row][132] (g stride)
    float* bias = (float*)(smem + SM_BIAS);  // [384]
    const uint32_t wsm = smem_u32(smem) + SM_W;

    const int tid = threadIdx.x, wid = tid >> 5, lane = tid & 31;
    const int wm = wid >> 1, wn = wid & 1;     // warp grid 4(m=batch) x 2(n)
    const int b0g = blockIdx.x * 4;
    const int r0 = lane >> 2;                  // row-in-frag 0..7
    const int c0 = (lane & 3) * 2;             // col pair base

    // ---- load x0 transposed + init state + bias ----
    {
        const float* Xb = X + (size_t)b0g * 1024;
        for (int i = tid; i < 4096; i += NT) {
            int b = i >> 10, f = (i >> 5) & 31, d = i & 31;
            float v = Xb[i];
            int row = b * 32 + d;
            x0t[row * 36 + f] = v;
            st[row * 132 + f] = v;     // layer-0 state = x0 (g = f)
        }
        for (int i = tid; i < 128; i += NT) {
            bias[i] = B0[i]; bias[128 + i] = B1[i]; bias[256 + i] = B2[i];
        }
    }

    // ---- W double-buffer prefetch of chunk 0 ----
    float4 wreg[2];
    {
        const float4* p = (const float4*)(WT_buf);
        wreg[0] = p[tid * 2]; wreg[1] = p[tid * 2 + 1];
    }
    __syncthreads();
    {
        #pragma unroll
        for (int j = 0; j < 2; ++j) {
            int u = tid * 2 + j;                 // 16B unit in compact chunk
            int term = u >> 8, n = (u >> 1) & 127, kh = u & 1;
            *(float4*)(smem + SM_W + term * WTERM + n * WROW + kh * 16) = wreg[j];
        }
    }
    __syncthreads();

    // B-frag lane decode (constant per thread)
    const int ntile_hl = (lane >> 4) & 1;
    const int kh = (lane >> 3) & 1;
    const int nrow_in = (lane & 7);

    int cg = 0;  // global chunk counter

    #pragma unroll 1
    for (int l = 0; l < 3; ++l) {
        const int lg2 = (l == 0) ? 1 : 3;        // chunks per f = fk/16
        const int nchunk = (l == 0) ? 64 : 256;

        float acc[2][8][4];
        #pragma unroll
        for (int fr = 0; fr < 2; ++fr)
            #pragma unroll
            for (int nt = 0; nt < 8; ++nt)
                #pragma unroll
                for (int q = 0; q < 4; ++q) acc[fr][nt][q] = 0.f;

        #pragma unroll 1
        for (int cc = 0; cc < nchunk; ++cc) {
            const uint32_t stage = wsm + (uint32_t)(cg & 1) * WSTAGE;

            // prefetch next chunk (global) into regs — latency hidden by MMAs
            if (cg + 1 < KCH) {
                const float4* p = (const float4*)(WT_buf + (size_t)(cg + 1) * CHUNK_GBYTES);
                wreg[0] = p[tid * 2]; wreg[1] = p[tid * 2 + 1];
            }

            // ---- Phase 1: ldsm t0 (Wh) for all 4 j ----
            uint32_t bh[4][4];
            #pragma unroll
            for (int j = 0; j < 4; ++j) {
                const int nrow = (wn * 8 + 2 * j + ntile_hl) * 8 + nrow_in;
                ldsm4(stage + nrow * WROW + kh * 16,
                      bh[j][0], bh[j][1], bh[j][2], bh[j][3]);
            }

            // ---- Phase 2: build A fragments (hi/lo) in registers ----
            const int f = cc >> lg2;
            const int g0 = ((cc & ((1 << lg2) - 1)) << 4) + c0;
            uint32_t ah[2][4], al[2][4];
            #pragma unroll
            for (int fr = 0; fr < 2; ++fr) {
                #pragma unroll
                for (int j2 = 0; j2 < 2; ++j2) {
                    const int row = wm * 32 + r0 + fr * 16 + j2 * 8;
                    const float x = x0t[row * 36 + f];
                    const float2 p0 = *(const float2*)(st + row * 132 + g0);
                    const float2 p1 = *(const float2*)(st + row * 132 + g0 + 8);
                    float z00 = x * p0.x, z01 = x * p0.y;
                    float z10 = x * p1.x, z11 = x * p1.y;
                    uint32_t h0 = pkbf(z00, z01), h1 = pkbf(z10, z11);
                    al[fr][j2]     = pkbf(z00 - bflo(h0), z01 - bfhi(h0));
                    al[fr][2 + j2] = pkbf(z10 - bflo(h1), z11 - bfhi(h1));
                    ah[fr][j2]     = h0;
                    ah[fr][2 + j2] = h1;
                }
            }

            // ---- Phase 3: MMAs t0 (Zh*Wh, Zl*Wh), RAW distance 4 ----
            #pragma unroll
            for (int j = 0; j < 4; ++j) {
                mma16816(acc[0][2 * j],     ah[0], bh[j][0], bh[j][1]);
                mma16816(acc[1][2 * j],     ah[1], bh[j][0], bh[j][1]);
                mma16816(acc[0][2 * j + 1], ah[0], bh[j][2], bh[j][3]);
                mma16816(acc[1][2 * j + 1], ah[1], bh[j][2], bh[j][3]);
                mma16816(acc[0][2 * j],     al[0], bh[j][0], bh[j][1]);
                mma16816(acc[1][2 * j],     al[1], bh[j][0], bh[j][1]);
                mma16816(acc[0][2 * j + 1], al[0], bh[j][2], bh[j][3]);
                mma16816(acc[1][2 * j + 1], al[1], bh[j][2], bh[j][3]);
            }

            // ---- Phase 4: t1 (Zh*Wl) ldsm + MMAs ----
            #pragma unroll
            for (int j = 0; j < 4; ++j) {
                const int nrow = (wn * 8 + 2 * j + ntile_hl) * 8 + nrow_in;
                uint32_t t0r, t1r, t2r, t3r;
                ldsm4(stage + WTERM + nrow * WROW + kh * 16, t0r, t1r, t2r, t3r);
                mma16816(acc[0][2 * j],     ah[0], t0r, t1r);
                mma16816(acc[1][2 * j],     ah[1], t0r, t1r);
                mma16816(acc[0][2 * j + 1], ah[0], t2r, t3r);
                mma16816(acc[1][2 * j + 1], ah[1], t2r, t3r);
            }

            // ---- store prefetched chunk to other stage ----
            if (cg + 1 < KCH) {
                #pragma unroll
                for (int j = 0; j < 2; ++j) {
                    int u = tid * 2 + j;
                    int term = u >> 8, n = (u >> 1) & 127, kh2 = u & 1;
                    *(float4*)(smem + SM_W + ((cg + 1) & 1) * WSTAGE +
                               term * WTERM + n * WROW + kh2 * 16) = wreg[j];
                }
            }
            __syncthreads();
            ++cg;
        }

        // ---- epilogue: output reduction (sum over d) + state update ----
        const int bgl = b0g + wm;
        #pragma unroll
        for (int nt = 0; nt < 8; ++nt) {
            float s0 = acc[0][nt][0] + acc[0][nt][2] + acc[1][nt][0] + acc[1][nt][2];
            float s1 = acc[0][nt][1] + acc[0][nt][3] + acc[1][nt][1] + acc[1][nt][3];
            #pragma unroll
            for (int off = 4; off <= 16; off <<= 1) {
                s0 += __shfl_xor_sync(0xffffffffu, s0, off);
                s1 += __shfl_xor_sync(0xffffffffu, s1, off);
            }
            if (lane < 4) {
                const int col = wn * 64 + nt * 8 + c0;
                float2 o;
                o.x = s0 + 32.0f * bias[l * 128 + col];
                o.y = s1 + 32.0f * bias[l * 128 + col + 1];
                *(float2*)(out + (size_t)bgl * 384 + l * 128 + col) = o;
            }
        }

        if (l < 2) {
            // state[row][h] = C[row][h] + bias_l[h]
            #pragma unroll
            for (int fr = 0; fr < 2; ++fr) {
                #pragma unroll
                for (int nt = 0; nt < 8; ++nt) {
                    const int col = wn * 64 + nt * 8 + c0;
                    const float bx = bias[l * 128 + col];
                    const float by = bias[l * 128 + col + 1];
                    const int rowa = wm * 32 + r0 + fr * 16;
                    float2 v0, v1;
                    v0.x = acc[fr][nt][0] + bx; v0.y = acc[fr][nt][1] + by;
                    v1.x = acc[fr][nt][2] + bx; v1.y = acc[fr][nt][3] + by;
                    *(float2*)(st + rowa * 132 + col)       = v0;
                    *(float2*)(st + (rowa + 8) * 132 + col) = v1;
                }
            }
            __syncthreads();   // state visible before next layer's A builds
        }
    }
}

extern "C" void kernel_launch(void* const* d_in, const int* in_sizes, int n_in,
                              void* d_out, int out_size) {
    const float* X  = (const float*)d_in[0];
    const float* W0 = (const float*)d_in[1];
    const float* W1 = (const float*)d_in[2];
    const float* W2 = (const float*)d_in[3];
    const float* B0 = (const float*)d_in[4];
    const float* B1 = (const float*)d_in[5];
    const float* B2 = (const float*)d_in[6];
    float* out = (float*)d_out;

    const int B = in_sizes[0] / 1024;

    cudaFuncSetAttribute(cin_hmma_kernel,
                         cudaFuncAttributeMaxDynamicSharedMemorySize, SMEM_TOTAL);

    prep_w<<<(9216 * 128 + 255) / 256, 256>>>(W0, W1, W2);
    cin_hmma_kernel<<<B / 4, NT, SMEM_TOTAL>>>(X, B0, B1, B2, out);
}

// round 7
// speedup vs baseline: 1.1391x; 1.1391x over previous
#include <cuda_runtime.h>
#include <cuda_bf16.h>
#include <cstdint>

// CIN (xDeepFM) fused 3-layer kernel via mma.sync (HMMA) bf16 3-term split.
// Round 6: cp.async W loads + A-build pipelined one chunk ahead, so the
// post-barrier stream is ldsm -> 48-MMA burst with no compute-free head phase.

#define NT 256
#define KCH 576             // total 16-wide k chunks: 64 + 256 + 256
#define WROW 48             // padded bytes per n-row (16k bf16 = 32B -> 48B)
#define WTERM (128 * WROW)  // 6144
#define CHUNK_BYTES (2 * WTERM)  // 12288 (hi term + lo term), gmem == smem layout

// smem byte offsets
#define SM_X0T   0                  // 128 rows * 36 f32 = 18432
#define SM_ST    18432              // 128 rows * 132 f32 = 67584
#define SM_W     86016              // 2 stages * 12288 = 24576
#define SM_BIAS  110592             // 384 f32 = 1536
#define SMEM_TOTAL 112128

__device__ __align__(16) unsigned char WT_buf[(size_t)KCH * CHUNK_BYTES]; // ~7MB

// ------------- helpers -------------
__device__ __forceinline__ uint32_t smem_u32(const void* p) {
    uint32_t a;
    asm("{ .reg .u64 t; cvta.to.shared.u64 t, %1; cvt.u32.u64 %0, t; }" : "=r"(a) : "l"(p));
    return a;
}
__device__ __forceinline__ uint32_t pkbf(float lo, float hi) {
    uint32_t r;  // first asm operand -> high half
    asm("cvt.rn.bf16x2.f32 %0, %1, %2;" : "=r"(r) : "f"(hi), "f"(lo));
    return r;
}
__device__ __forceinline__ float bflo(uint32_t p) { return __uint_as_float(p << 16); }
__device__ __forceinline__ float bfhi(uint32_t p) { return __uint_as_float(p & 0xffff0000u); }

__device__ __forceinline__ void ldsm4(uint32_t a, uint32_t& r0, uint32_t& r1,
                                      uint32_t& r2, uint32_t& r3) {
    asm volatile("ldmatrix.sync.aligned.m8n8.x4.shared.b16 {%0,%1,%2,%3}, [%4];"
                 : "=r"(r0), "=r"(r1), "=r"(r2), "=r"(r3) : "r"(a));
}
__device__ __forceinline__ void mma16816(float* c, const uint32_t* a, uint32_t b0, uint32_t b1) {
    asm volatile("mma.sync.aligned.m16n8k16.row.col.f32.bf16.bf16.f32 "
                 "{%0,%1,%2,%3}, {%4,%5,%6,%7}, {%8,%9}, {%0,%1,%2,%3};"
                 : "+f"(c[0]), "+f"(c[1]), "+f"(c[2]), "+f"(c[3])
                 : "r"(a[0]), "r"(a[1]), "r"(a[2]), "r"(a[3]), "r"(b0), "r"(b1));
}
__device__ __forceinline__ void cpasync16(uint32_t dst, const void* src) {
    asm volatile("cp.async.cg.shared.global [%0], [%1], 16;" :: "r"(dst), "l"(src) : "memory");
}
#define CP_COMMIT() asm volatile("cp.async.commit_group;" ::: "memory")
#define CP_WAIT0()  asm volatile("cp.async.wait_group 0;" ::: "memory")
#define CP_WAIT1()  asm volatile("cp.async.wait_group 1;" ::: "memory")

// ------------- prep: split W -> bf16 hi/lo, padded chunk layout == smem -------------
__global__ void prep_w(const float* __restrict__ W0, const float* __restrict__ W1,
                       const float* __restrict__ W2) {
    int i = blockIdx.x * blockDim.x + threadIdx.x;   // over 9216*128
    if (i >= 9216 * 128) return;
    int k = i >> 7, n = i & 127;
    float w;
    if (k < 1024)      w = W0[k * 128 + n];
    else if (k < 5120) w = W1[(k - 1024) * 128 + n];
    else               w = W2[(k - 5120) * 128 + n];
    __nv_bfloat16 hb = __float2bfloat16(w);
    __nv_bfloat16 lb = __float2bfloat16(w - __bfloat162float(hb));
    int c = k >> 4, kk = k & 15;
    unsigned char* base = WT_buf + (size_t)c * CHUNK_BYTES + n * WROW + kk * 2;
    *(__nv_bfloat16*)(base)         = hb;   // hi term
    *(__nv_bfloat16*)(base + WTERM) = lb;   // lo term
}

// ------------- main kernel -------------
__global__ void __launch_bounds__(NT, 2)
cin_hmma_kernel(const float* __restrict__ X,
                const float* __restrict__ B0, const float* __restrict__ B1,
                const float* __restrict__ B2, float* __restrict__ out)
{
    extern __shared__ __align__(16) char smem[];
    float* x0t  = (float*)(smem + SM_X0T);   // [row][36] (f stride)
    float* st   = (float*)(smem + SM_ST);    // [row][132] (g stride)
    float* bias = (float*)(smem + SM_BIAS);  // [384]
    const uint32_t wsm = smem_u32(smem) + SM_W;

    const int tid = threadIdx.x, wid = tid >> 5, lane = tid & 31;
    const int wm = wid >> 1, wn = wid & 1;     // warp grid 4(m=batch) x 2(n)
    const int b0g = blockIdx.x * 4;
    const int r0 = lane >> 2;                  // row-in-frag 0..7
    const int c0 = (lane & 3) * 2;             // col pair base

    // ---- issue cp.async for chunks 0 and 1 immediately ----
    {
        const unsigned char* src0 = WT_buf + tid * 16;
        cpasync16(wsm + tid * 16,        src0);
        cpasync16(wsm + tid * 16 + 4096, src0 + 4096);
        cpasync16(wsm + tid * 16 + 8192, src0 + 8192);
        CP_COMMIT();
        const unsigned char* src1 = WT_buf + CHUNK_BYTES + tid * 16;
        cpasync16(wsm + CHUNK_BYTES + tid * 16,        src1);
        cpasync16(wsm + CHUNK_BYTES + tid * 16 + 4096, src1 + 4096);
        cpasync16(wsm + CHUNK_BYTES + tid * 16 + 8192, src1 + 8192);
        CP_COMMIT();
    }

    // ---- load x0 transposed + init state + bias ----
    {
        const float* Xb = X + (size_t)b0g * 1024;
        for (int i = tid; i < 4096; i += NT) {
            int b = i >> 10, f = (i >> 5) & 31, d = i & 31;
            float v = Xb[i];
            int row = b * 32 + d;
            x0t[row * 36 + f] = v;
            st[row * 132 + f] = v;     // layer-0 state = x0 (g = f)
        }
        for (int i = tid; i < 128; i += NT) {
            bias[i] = B0[i]; bias[128 + i] = B1[i]; bias[256 + i] = B2[i];
        }
    }
    CP_WAIT1();          // chunk 0 landed
    __syncthreads();     // x0/st/bias + chunk 0 visible

    // B-frag lane decode -> per-j ldsm byte offsets within a stage (t0 term)
    const int kh16 = ((lane >> 3) & 1) * 16;
    uint32_t nroff[4];
    #pragma unroll
    for (int j = 0; j < 4; ++j) {
        const int nrow = (wn * 8 + 2 * j + ((lane >> 4) & 1)) * 8 + (lane & 7);
        nroff[j] = (uint32_t)(nrow * WROW + kh16);
    }

    int cg = 0;  // global chunk counter

    #pragma unroll 1
    for (int l = 0; l < 3; ++l) {
        const int lg2 = (l == 0) ? 1 : 3;        // chunks per f = fk/16
        const int nchunk = (l == 0) ? 64 : 256;

        float acc[2][8][4];
        #pragma unroll
        for (int fr = 0; fr < 2; ++fr)
            #pragma unroll
            for (int nt = 0; nt < 8; ++nt)
                #pragma unroll
                for (int q = 0; q < 4; ++q) acc[fr][nt][q] = 0.f;

        uint32_t ah[2][4], al[2][4];

        // A-build helper (reads x0t/st, layer-stable within the chunk loop)
        auto build_A = [&](int cc) {
            const int f = cc >> lg2;
            const int g0 = ((cc & ((1 << lg2) - 1)) << 4) + c0;
            #pragma unroll
            for (int fr = 0; fr < 2; ++fr) {
                #pragma unroll
                for (int j2 = 0; j2 < 2; ++j2) {
                    const int row = wm * 32 + r0 + fr * 16 + j2 * 8;
                    const float x = x0t[row * 36 + f];
                    const float2 p0 = *(const float2*)(st + row * 132 + g0);
                    const float2 p1 = *(const float2*)(st + row * 132 + g0 + 8);
                    float z00 = x * p0.x, z01 = x * p0.y;
                    float z10 = x * p1.x, z11 = x * p1.y;
                    uint32_t h0 = pkbf(z00, z01), h1 = pkbf(z10, z11);
                    al[fr][j2]     = pkbf(z00 - bflo(h0), z01 - bfhi(h0));
                    al[fr][2 + j2] = pkbf(z10 - bflo(h1), z11 - bfhi(h1));
                    ah[fr][j2]     = h0;
                    ah[fr][2 + j2] = h1;
                }
            }
        };

        build_A(0);   // state is synced at this point

        #pragma unroll 1
        for (int cc = 0; cc < nchunk; ++cc) {
            const uint32_t stage = wsm + (uint32_t)(cg & 1) * CHUNK_BYTES;

            // ---- ldsm all 8 (t0 hi-term + t1 lo-term) ----
            uint32_t bh[4][4], bl[4][4];
            #pragma unroll
            for (int j = 0; j < 4; ++j)
                ldsm4(stage + nroff[j], bh[j][0], bh[j][1], bh[j][2], bh[j][3]);
            #pragma unroll
            for (int j = 0; j < 4; ++j)
                ldsm4(stage + WTERM + nroff[j], bl[j][0], bl[j][1], bl[j][2], bl[j][3]);

            // ---- 48-MMA burst ----
            #pragma unroll
            for (int j = 0; j < 4; ++j) {
                mma16816(acc[0][2 * j],     ah[0], bh[j][0], bh[j][1]);
                mma16816(acc[1][2 * j],     ah[1], bh[j][0], bh[j][1]);
                mma16816(acc[0][2 * j + 1], ah[0], bh[j][2], bh[j][3]);
                mma16816(acc[1][2 * j + 1], ah[1], bh[j][2], bh[j][3]);
                mma16816(acc[0][2 * j],     al[0], bh[j][0], bh[j][1]);
                mma16816(acc[1][2 * j],     al[1], bh[j][0], bh[j][1]);
                mma16816(acc[0][2 * j + 1], al[0], bh[j][2], bh[j][3]);
                mma16816(acc[1][2 * j + 1], al[1], bh[j][2], bh[j][3]);
                mma16816(acc[0][2 * j],     ah[0], bl[j][0], bl[j][1]);
                mma16816(acc[1][2 * j],     ah[1], bl[j][0], bl[j][1]);
                mma16816(acc[0][2 * j + 1], ah[0], bl[j][2], bl[j][3]);
                mma16816(acc[1][2 * j + 1], ah[1], bl[j][2], bl[j][3]);
            }

            // ---- A-build for next chunk (hidden under queued tensor work) ----
            if (cc + 1 < nchunk) build_A(cc + 1);

            // ---- rotate W stages ----
            CP_WAIT0();        // chunk cg+1 (issued last iter) is in smem
            __syncthreads();   // chunk cg+1 visible; all warps done with stage cg&1
            if (cg + 2 < KCH) {
                const unsigned char* src = WT_buf + (size_t)(cg + 2) * CHUNK_BYTES + tid * 16;
                cpasync16(stage + tid * 16,        src);
                cpasync16(stage + tid * 16 + 4096, src + 4096);
                cpasync16(stage + tid * 16 + 8192, src + 8192);
                CP_COMMIT();
            }
            ++cg;
        }

        // ---- epilogue: output reduction (sum over d) + state update ----
        const int bgl = b0g + wm;
        #pragma unroll
        for (int nt = 0; nt < 8; ++nt) {
            float s0 = acc[0][nt][0] + acc[0][nt][2] + acc[1][nt][0] + acc[1][nt][2];
            float s1 = acc[0][nt][1] + acc[0][nt][3] + acc[1][nt][1] + acc[1][nt][3];
            #pragma unroll
            for (int off = 4; off <= 16; off <<= 1) {
                s0 += __shfl_xor_sync(0xffffffffu, s0, off);
                s1 += __shfl_xor_sync(0xffffffffu, s1, off);
            }
            if (lane < 4) {
                const int col = wn * 64 + nt * 8 + c0;
                float2 o;
                o.x = s0 + 32.0f * bias[l * 128 + col];
                o.y = s1 + 32.0f * bias[l * 128 + col + 1];
                *(float2*)(out + (size_t)bgl * 384 + l * 128 + col) = o;
            }
        }

        if (l < 2) {
            // state[row][h] = C[row][h] + bias_l[h]
            #pragma unroll
            for (int fr = 0; fr < 2; ++fr) {
                #pragma unroll
                for (int nt = 0; nt < 8; ++nt) {
                    const int col = wn * 64 + nt * 8 + c0;
                    const float bx = bias[l * 128 + col];
                    const float by = bias[l * 128 + col + 1];
                    const int rowa = wm * 32 + r0 + fr * 16;
                    float2 v0, v1;
                    v0.x = acc[fr][nt][0] + bx; v0.y = acc[fr][nt][1] + by;
                    v1.x = acc[fr][nt][2] + bx; v1.y = acc[fr][nt][3] + by;
                    *(float2*)(st + rowa * 132 + col)       = v0;
                    *(float2*)(st + (rowa + 8) * 132 + col) = v1;
                }
            }
            __syncthreads();   // state visible before next layer's A builds
        }
    }
}

extern "C" void kernel_launch(void* const* d_in, const int* in_sizes, int n_in,
                              void* d_out, int out_size) {
    const float* X  = (const float*)d_in[0];
    const float* W0 = (const float*)d_in[1];
    const float* W1 = (const float*)d_in[2];
    const float* W2 = (const float*)d_in[3];
    const float* B0 = (const float*)d_in[4];
    const float* B1 = (const float*)d_in[5];
    const float* B2 = (const float*)d_in[6];
    float* out = (float*)d_out;

    const int B = in_sizes[0] / 1024;

    cudaFuncSetAttribute(cin_hmma_kernel,
                         cudaFuncAttributeMaxDynamicSharedMemorySize, SMEM_TOTAL);

    prep_w<<<(9216 * 128 + 255) / 256, 256>>>(W0, W1, W2);
    cin_hmma_kernel<<<B / 4, NT, SMEM_TOTAL>>>(X, B0, B1, B2, out);
}

// round 8
// speedup vs baseline: 1.2360x; 1.0851x over previous
#include <cuda_runtime.h>
#include <cuda_bf16.h>
#include <cstdint>

// CIN (xDeepFM) fused 3-layer kernel via mma.sync (HMMA) bf16 3-term split.
// Round 7: 3-stage W ring (swizzled, 8KB/chunk), register-double-buffered
// B-fragments (ldsm for chunk i+1 issued before the barrier), cp.async issued
// 2 chunks ahead. Post-barrier instruction stream starts directly with MMAs.

#define NT 256
#define KCH 576                 // total 16-wide k chunks: 64 + 256 + 256
#define WTERM 4096              // 128 n-rows * 32B (16 bf16), swizzled
#define CHUNK_BYTES (2 * WTERM) // 8192: hi term + lo term
#define NSTAGE 3

// smem byte offsets
#define SM_X0T   0                  // 128 rows * 36 f32 = 18432
#define SM_ST    18432              // 128 rows * 132 f32 = 67584
#define SM_W     86016              // 3 stages * 8192 = 24576
#define SM_BIAS  110592             // 384 f32 = 1536
#define SMEM_TOTAL 112128

__device__ __align__(16) unsigned char WT_buf[(size_t)KCH * CHUNK_BYTES]; // 4.7MB

// ------------- helpers -------------
__device__ __forceinline__ uint32_t smem_u32(const void* p) {
    uint32_t a;
    asm("{ .reg .u64 t; cvta.to.shared.u64 t, %1; cvt.u32.u64 %0, t; }" : "=r"(a) : "l"(p));
    return a;
}
__device__ __forceinline__ uint32_t pkbf(float lo, float hi) {
    uint32_t r;  // first asm operand -> high half
    asm("cvt.rn.bf16x2.f32 %0, %1, %2;" : "=r"(r) : "f"(hi), "f"(lo));
    return r;
}
__device__ __forceinline__ float bflo(uint32_t p) { return __uint_as_float(p << 16); }
__device__ __forceinline__ float bfhi(uint32_t p) { return __uint_as_float(p & 0xffff0000u); }

__device__ __forceinline__ void ldsm4(uint32_t a, uint32_t& r0, uint32_t& r1,
                                      uint32_t& r2, uint32_t& r3) {
    asm volatile("ldmatrix.sync.aligned.m8n8.x4.shared.b16 {%0,%1,%2,%3}, [%4];"
                 : "=r"(r0), "=r"(r1), "=r"(r2), "=r"(r3) : "r"(a));
}
__device__ __forceinline__ void mma16816(float* c, const uint32_t* a, uint32_t b0, uint32_t b1) {
    asm volatile("mma.sync.aligned.m16n8k16.row.col.f32.bf16.bf16.f32 "
                 "{%0,%1,%2,%3}, {%4,%5,%6,%7}, {%8,%9}, {%0,%1,%2,%3};"
                 : "+f"(c[0]), "+f"(c[1]), "+f"(c[2]), "+f"(c[3])
                 : "r"(a[0]), "r"(a[1]), "r"(a[2]), "r"(a[3]), "r"(b0), "r"(b1));
}
__device__ __forceinline__ void cpasync16(uint32_t dst, const void* src) {
    asm volatile("cp.async.cg.shared.global [%0], [%1], 16;" :: "r"(dst), "l"(src) : "memory");
}
#define CP_COMMIT() asm volatile("cp.async.commit_group;" ::: "memory")
#define CP_WAIT1()  asm volatile("cp.async.wait_group 1;" ::: "memory")

// swizzled byte offset of the 16B half (n-row, khalf) within one term
__device__ __host__ __forceinline__ int wsw(int n, int khalf) {
    return n * 32 + ((khalf ^ ((n >> 2) & 1)) << 4);
}

// ------------- prep: split W -> bf16 hi/lo, swizzled chunk layout == smem -------------
__global__ void prep_w(const float* __restrict__ W0, const float* __restrict__ W1,
                       const float* __restrict__ W2) {
    int i = blockIdx.x * blockDim.x + threadIdx.x;   // over 9216*128
    if (i >= 9216 * 128) return;
    int k = i >> 7, n = i & 127;
    float w;
    if (k < 1024)      w = W0[k * 128 + n];
    else if (k < 5120) w = W1[(k - 1024) * 128 + n];
    else               w = W2[(k - 5120) * 128 + n];
    __nv_bfloat16 hb = __float2bfloat16(w);
    __nv_bfloat16 lb = __float2bfloat16(w - __bfloat162float(hb));
    int c = k >> 4, kk = k & 15;
    int off = wsw(n, kk >> 3) + (kk & 7) * 2;
    unsigned char* base = WT_buf + (size_t)c * CHUNK_BYTES + off;
    *(__nv_bfloat16*)(base)         = hb;   // hi term
    *(__nv_bfloat16*)(base + WTERM) = lb;   // lo term
}

// ------------- main kernel -------------
__global__ void __launch_bounds__(NT, 2)
cin_hmma_kernel(const float* __restrict__ X,
                const float* __restrict__ B0, const float* __restrict__ B1,
                const float* __restrict__ B2, float* __restrict__ out)
{
    extern __shared__ __align__(16) char smem[];
    float* x0t  = (float*)(smem + SM_X0T);   // [row][36] (f stride)
    float* st   = (float*)(smem + SM_ST);    // [row][132] (g stride)
    float* bias = (float*)(smem + SM_BIAS);  // [384]
    const uint32_t wsm = smem_u32(smem) + SM_W;

    const int tid = threadIdx.x, wid = tid >> 5, lane = tid & 31;
    const int wm = wid >> 1, wn = wid & 1;     // warp grid 4(m=batch) x 2(n)
    const int b0g = blockIdx.x * 4;
    const int r0 = lane >> 2;                  // row-in-frag 0..7
    const int c0 = (lane & 3) * 2;             // col pair base

    // ---- issue cp.async for chunks 0 and 1 immediately ----
    {
        const unsigned char* s0 = WT_buf + tid * 16;
        cpasync16(wsm + tid * 16,        s0);
        cpasync16(wsm + tid * 16 + 4096, s0 + 4096);
        CP_COMMIT();
        const unsigned char* s1 = WT_buf + CHUNK_BYTES + tid * 16;
        cpasync16(wsm + CHUNK_BYTES + tid * 16,        s1);
        cpasync16(wsm + CHUNK_BYTES + tid * 16 + 4096, s1 + 4096);
        CP_COMMIT();
    }

    // ---- load x0 transposed + init state + bias ----
    {
        const float* Xb = X + (size_t)b0g * 1024;
        for (int i = tid; i < 4096; i += NT) {
            int b = i >> 10, f = (i >> 5) & 31, d = i & 31;
            float v = Xb[i];
            int row = b * 32 + d;
            x0t[row * 36 + f] = v;
            st[row * 132 + f] = v;     // layer-0 state = x0 (g = f)
        }
        for (int i = tid; i < 128; i += NT) {
            bias[i] = B0[i]; bias[128 + i] = B1[i]; bias[256 + i] = B2[i];
        }
    }
    CP_WAIT1();          // chunk 0 landed (chunk 1 may still be in flight)
    __syncthreads();     // x0/st/bias + chunk 0 visible

    // per-j ldsm swizzled offsets within a term
    const int kh = (lane >> 3) & 1;
    uint32_t nroff[4];
    #pragma unroll
    for (int j = 0; j < 4; ++j) {
        const int nrow = (wn * 8 + 2 * j + ((lane >> 4) & 1)) * 8 + (lane & 7);
        nroff[j] = (uint32_t)wsw(nrow, kh);
    }

    uint32_t bh[4][4], bl[4][4];    // current chunk's B fragments
    uint32_t ah[2][4], al[2][4];    // current chunk's A fragments

    // prime B for chunk 0 (stage 0)
    #pragma unroll
    for (int j = 0; j < 4; ++j)
        ldsm4(wsm + nroff[j], bh[j][0], bh[j][1], bh[j][2], bh[j][3]);
    #pragma unroll
    for (int j = 0; j < 4; ++j)
        ldsm4(wsm + WTERM + nroff[j], bl[j][0], bl[j][1], bl[j][2], bl[j][3]);

    int cg = 0;      // global chunk counter
    int scur = 0;    // stage of current chunk
    int swr = 2;     // stage cp.async writes (cg+2)

    #pragma unroll 1
    for (int l = 0; l < 3; ++l) {
        const int lg2 = (l == 0) ? 1 : 3;        // chunks per f = fk/16
        const int nchunk = (l == 0) ? 64 : 256;

        float acc[2][8][4];
        #pragma unroll
        for (int fr = 0; fr < 2; ++fr)
            #pragma unroll
            for (int nt = 0; nt < 8; ++nt)
                #pragma unroll
                for (int q = 0; q < 4; ++q) acc[fr][nt][q] = 0.f;

        auto build_A = [&](int cc) {
            const int f = cc >> lg2;
            const int g0 = ((cc & ((1 << lg2) - 1)) << 4) + c0;
            #pragma unroll
            for (int fr = 0; fr < 2; ++fr) {
                #pragma unroll
                for (int j2 = 0; j2 < 2; ++j2) {
                    const int row = wm * 32 + r0 + fr * 16 + j2 * 8;
                    const float x = x0t[row * 36 + f];
                    const float2 p0 = *(const float2*)(st + row * 132 + g0);
                    const float2 p1 = *(const float2*)(st + row * 132 + g0 + 8);
                    float z00 = x * p0.x, z01 = x * p0.y;
                    float z10 = x * p1.x, z11 = x * p1.y;
                    uint32_t h0 = pkbf(z00, z01), h1 = pkbf(z10, z11);
                    al[fr][j2]     = pkbf(z00 - bflo(h0), z01 - bfhi(h0));
                    al[fr][2 + j2] = pkbf(z10 - bflo(h1), z11 - bfhi(h1));
                    ah[fr][j2]     = h0;
                    ah[fr][2 + j2] = h1;
                }
            }
        };

        build_A(0);   // state is synced at this point

        #pragma unroll 1
        for (int cc = 0; cc < nchunk; ++cc) {
            // ---- issue cp.async for chunk cg+2 (stage swr is WAR-safe since
            //      the barrier at the end of the previous iteration) ----
            if (cg + 2 < KCH) {
                const unsigned char* src = WT_buf + (size_t)(cg + 2) * CHUNK_BYTES + tid * 16;
                const uint32_t dst = wsm + (uint32_t)swr * CHUNK_BYTES + tid * 16;
                cpasync16(dst,        src);
                cpasync16(dst + 4096, src + 4096);
                CP_COMMIT();
            }

            // ---- 48-MMA burst for chunk cg (A and B already in registers) ----
            #pragma unroll
            for (int j = 0; j < 4; ++j) {
                mma16816(acc[0][2 * j],     ah[0], bh[j][0], bh[j][1]);
                mma16816(acc[1][2 * j],     ah[1], bh[j][0], bh[j][1]);
                mma16816(acc[0][2 * j + 1], ah[0], bh[j][2], bh[j][3]);
                mma16816(acc[1][2 * j + 1], ah[1], bh[j][2], bh[j][3]);
                mma16816(acc[0][2 * j],     al[0], bh[j][0], bh[j][1]);
                mma16816(acc[1][2 * j],     al[1], bh[j][0], bh[j][1]);
                mma16816(acc[0][2 * j + 1], al[0], bh[j][2], bh[j][3]);
                mma16816(acc[1][2 * j + 1], al[1], bh[j][2], bh[j][3]);
                mma16816(acc[0][2 * j],     ah[0], bl[j][0], bl[j][1]);
                mma16816(acc[1][2 * j],     ah[1], bl[j][0], bl[j][1]);
                mma16816(acc[0][2 * j + 1], ah[0], bl[j][2], bl[j][3]);
                mma16816(acc[1][2 * j + 1], ah[1], bl[j][2], bl[j][3]);
            }

            // ---- A for next chunk of this layer ----
            if (cc + 1 < nchunk) build_A(cc + 1);

            // ---- B for chunk cg+1 (stage scur+1; its cp group has ~2 chunks
            //      of slack; wait_group 1 leaves cg+2's group pending) ----
            if (cg + 1 < KCH) {
                CP_WAIT1();
                const uint32_t snx = wsm + (uint32_t)((scur + 1) % NSTAGE) * CHUNK_BYTES;
                #pragma unroll
                for (int j = 0; j < 4; ++j)
                    ldsm4(snx + nroff[j], bh[j][0], bh[j][1], bh[j][2], bh[j][3]);
                #pragma unroll
                for (int j = 0; j < 4; ++j)
                    ldsm4(snx + WTERM + nroff[j], bl[j][0], bl[j][1], bl[j][2], bl[j][3]);
            }

            // ---- WAR fence: all warps done reading stage scur ----
            __syncthreads();

            scur = (scur + 1) % NSTAGE;
            swr  = (swr + 1) % NSTAGE;
            ++cg;
        }

        // ---- epilogue: output reduction (sum over d) + state update ----
        const int bgl = b0g + wm;
        #pragma unroll
        for (int nt = 0; nt < 8; ++nt) {
            float s0 = acc[0][nt][0] + acc[0][nt][2] + acc[1][nt][0] + acc[1][nt][2];
            float s1 = acc[0][nt][1] + acc[0][nt][3] + acc[1][nt][1] + acc[1][nt][3];
            #pragma unroll
            for (int off = 4; off <= 16; off <<= 1) {
                s0 += __shfl_xor_sync(0xffffffffu, s0, off);
                s1 += __shfl_xor_sync(0xffffffffu, s1, off);
            }
            if (lane < 4) {
                const int col = wn * 64 + nt * 8 + c0;
                float2 o;
                o.x = s0 + 32.0f * bias[l * 128 + col];
                o.y = s1 + 32.0f * bias[l * 128 + col + 1];
                *(float2*)(out + (size_t)bgl * 384 + l * 128 + col) = o;
            }
        }

        if (l < 2) {
            // state[row][h] = C[row][h] + bias_l[h]
            #pragma unroll
            for (int fr = 0; fr < 2; ++fr) {
                #pragma unroll
                for (int nt = 0; nt < 8; ++nt) {
                    const int col = wn * 64 + nt * 8 + c0;
                    const float bx = bias[l * 128 + col];
                    const float by = bias[l * 128 + col + 1];
                    const int rowa = wm * 32 + r0 + fr * 16;
                    float2 v0, v1;
                    v0.x = acc[fr][nt][0] + bx; v0.y = acc[fr][nt][1] + by;
                    v1.x = acc[fr][nt][2] + bx; v1.y = acc[fr][nt][3] + by;
                    *(float2*)(st + rowa * 132 + col)       = v0;
                    *(float2*)(st + (rowa + 8) * 132 + col) = v1;
                }
            }
            __syncthreads();   // state visible before next layer's A builds
        }
    }
}

extern "C" void kernel_launch(void* const* d_in, const int* in_sizes, int n_in,
                              void* d_out, int out_size) {
    const float* X  = (const float*)d_in[0];
    const float* W0 = (const float*)d_in[1];
    const float* W1 = (const float*)d_in[2];
    const float* W2 = (const float*)d_in[3];
    const float* B0 = (const float*)d_in[4];
    const float* B1 = (const float*)d_in[5];
    const float* B2 = (const float*)d_in[6];
    float* out = (float*)d_out;

    const int B = in_sizes[0] / 1024;

    cudaFuncSetAttribute(cin_hmma_kernel,
                         cudaFuncAttributeMaxDynamicSharedMemorySize, SMEM_TOTAL);

    prep_w<<<(9216 * 128 + 255) / 256, 256>>>(W0, W1, W2);
    cin_hmma_kernel<<<B / 4, NT, SMEM_TOTAL>>>(X, B0, B1, B2, out);
}